// round 2
// baseline (speedup 1.0000x reference)
#include <cuda_runtime.h>

#define TPB 128
#define ROW 63   // 21 joints * 3

__global__ void __launch_bounds__(TPB, 1)
kin_kernel(const float* __restrict__ joints,
           const float* __restrict__ tempJ,
           float* __restrict__ out, int n)
{
    __shared__ float sm[TPB * ROW];   // 32256 B
    const int tid = threadIdx.x;
    const long long total = (long long)n * ROW;
    const long long gbase = (long long)blockIdx.x * (TPB * ROW);
    const bool active = ((long long)blockIdx.x * TPB + tid) < n;
    const int base = tid * ROW;

    // ---------------- stage joints (coalesced float4) ----------------
    {
        #pragma unroll
        for (int i = 0; i < 16; ++i) {
            int idx = (i * TPB + tid) * 4;
            if (idx < TPB * ROW) {
                long long g = gbase + idx;
                if (g + 3 < total) {
                    *reinterpret_cast<float4*>(&sm[idx]) =
                        *reinterpret_cast<const float4*>(&joints[g]);
                } else {
                    #pragma unroll
                    for (int j = 0; j < 4; ++j)
                        if (g + j < total) sm[idx + j] = joints[g + j];
                }
            }
        }
    }
    __syncthreads();

    // ---------------- extract per-thread joint data ----------------
    float wx = 0.f, wy = 0.f, wz = 0.f;
    float jp[5][3];     // palm points 1,4,7,10,13 (centered); joint 0 contributes 0 to H
    float jc[15][3];    // children, in chain order
    const int PALM5[5] = {1, 4, 7, 10, 13};
    const int CH[15] = {2,3,17, 5,6,18, 8,9,20, 11,12,19, 14,15,16};
    if (active) {
        wx = sm[base + 0]; wy = sm[base + 1]; wz = sm[base + 2];
        #pragma unroll
        for (int p = 0; p < 5; ++p) {
            jp[p][0] = sm[base + 3 * PALM5[p] + 0] - wx;
            jp[p][1] = sm[base + 3 * PALM5[p] + 1] - wy;
            jp[p][2] = sm[base + 3 * PALM5[p] + 2] - wz;
        }
        #pragma unroll
        for (int i = 0; i < 15; ++i) {
            jc[i][0] = sm[base + 3 * CH[i] + 0] - wx;
            jc[i][1] = sm[base + 3 * CH[i] + 1] - wy;
            jc[i][2] = sm[base + 3 * CH[i] + 2] - wz;
        }
    }
    __syncthreads();

    // ---------------- stage tempJ (coalesced float4) ----------------
    {
        #pragma unroll
        for (int i = 0; i < 16; ++i) {
            int idx = (i * TPB + tid) * 4;
            if (idx < TPB * ROW) {
                long long g = gbase + idx;
                if (g + 3 < total) {
                    *reinterpret_cast<float4*>(&sm[idx]) =
                        *reinterpret_cast<const float4*>(&tempJ[g]);
                } else {
                    #pragma unroll
                    for (int j = 0; j < 4; ++j)
                        if (g + j < total) sm[idx + j] = tempJ[g + j];
                }
            }
        }
    }
    __syncthreads();

    if (active) {
        const float t0x = sm[base + 0], t0y = sm[base + 1], t0z = sm[base + 2];

        // ---------------- H = sum_palm src ⊗ dst  (src=template centered, dst=J) ----
        float H[3][3] = {{0,0,0},{0,0,0},{0,0,0}};
        #pragma unroll
        for (int p = 0; p < 5; ++p) {
            float sx = sm[base + 3 * PALM5[p] + 0] - t0x;
            float sy = sm[base + 3 * PALM5[p] + 1] - t0y;
            float sz = sm[base + 3 * PALM5[p] + 2] - t0z;
            H[0][0] += sx * jp[p][0]; H[0][1] += sx * jp[p][1]; H[0][2] += sx * jp[p][2];
            H[1][0] += sy * jp[p][0]; H[1][1] += sy * jp[p][1]; H[1][2] += sy * jp[p][2];
            H[2][0] += sz * jp[p][0]; H[2][1] += sz * jp[p][1]; H[2][2] += sz * jp[p][2];
        }

        // ---------------- A = H^T H, Jacobi eigen (V accumulates rotations, det=+1) --
        float A[3][3];
        #pragma unroll
        for (int a = 0; a < 3; ++a)
            #pragma unroll
            for (int b = 0; b < 3; ++b)
                A[a][b] = H[0][a]*H[0][b] + H[1][a]*H[1][b] + H[2][a]*H[2][b];

        float V[3][3] = {{1,0,0},{0,1,0},{0,0,1}};
        #pragma unroll
        for (int sweep = 0; sweep < 5; ++sweep) {
            #pragma unroll
            for (int pair = 0; pair < 3; ++pair) {
                const int p = (pair == 2) ? 1 : 0;
                const int q = (pair == 0) ? 1 : 2;
                float apq = A[p][q];
                if (fabsf(apq) > 1e-30f) {
                    float tau = (A[q][q] - A[p][p]) / (2.0f * apq);
                    float t = 1.0f / (fabsf(tau) + sqrtf(1.0f + tau * tau));
                    t = copysignf(t, tau);
                    float c = rsqrtf(1.0f + t * t);
                    float s = t * c;
                    float app = A[p][p], aqq = A[q][q];
                    A[p][p] = app - t * apq;
                    A[q][q] = aqq + t * apq;
                    A[p][q] = 0.f; A[q][p] = 0.f;
                    const int r = 3 - p - q;
                    float arp = A[r][p], arq = A[r][q];
                    A[r][p] = c * arp - s * arq; A[p][r] = A[r][p];
                    A[r][q] = s * arp + c * arq; A[q][r] = A[r][q];
                    #pragma unroll
                    for (int k = 0; k < 3; ++k) {
                        float vp = V[k][p], vq = V[k][q];
                        V[k][p] = c * vp - s * vq;
                        V[k][q] = s * vp + c * vq;
                    }
                }
            }
        }

        // sort: i0 = largest eigenvalue, i1 = second (branchless column selects)
        float e0 = A[0][0], e1 = A[1][1], e2 = A[2][2];
        int i0 = 0; float em = e0;
        if (e1 > em) { i0 = 1; em = e1; }
        if (e2 > em) { i0 = 2; em = e2; }
        const int a1 = (i0 + 1) % 3, b1 = (i0 + 2) % 3;
        float ea = (a1 == 0) ? e0 : (a1 == 1) ? e1 : e2;
        float eb = (b1 == 0) ? e0 : (b1 == 1) ? e1 : e2;
        const int i1 = (ea >= eb) ? a1 : b1;

        float v1[3], v2[3], v3[3];
        #pragma unroll
        for (int k = 0; k < 3; ++k) {
            v1[k] = (i0 == 0) ? V[k][0] : (i0 == 1) ? V[k][1] : V[k][2];
            v2[k] = (i1 == 0) ? V[k][0] : (i1 == 1) ? V[k][1] : V[k][2];
        }
        v3[0] = v1[1]*v2[2] - v1[2]*v2[1];
        v3[1] = v1[2]*v2[0] - v1[0]*v2[2];
        v3[2] = v1[0]*v2[1] - v1[1]*v2[0];

        // u1 = norm(H v1); u2 = norm(H v2 - proj); u3 = u1 x u2
        float u1[3], u2[3], u3[3];
        #pragma unroll
        for (int k = 0; k < 3; ++k)
            u1[k] = H[k][0]*v1[0] + H[k][1]*v1[1] + H[k][2]*v1[2];
        {
            float inv = rsqrtf(u1[0]*u1[0] + u1[1]*u1[1] + u1[2]*u1[2] + 1e-30f);
            u1[0] *= inv; u1[1] *= inv; u1[2] *= inv;
        }
        #pragma unroll
        for (int k = 0; k < 3; ++k)
            u2[k] = H[k][0]*v2[0] + H[k][1]*v2[1] + H[k][2]*v2[2];
        {
            float pr = u1[0]*u2[0] + u1[1]*u2[1] + u1[2]*u2[2];
            u2[0] -= pr * u1[0]; u2[1] -= pr * u1[1]; u2[2] -= pr * u1[2];
            float inv = rsqrtf(u2[0]*u2[0] + u2[1]*u2[1] + u2[2]*u2[2] + 1e-30f);
            u2[0] *= inv; u2[1] *= inv; u2[2] *= inv;
        }
        u3[0] = u1[1]*u2[2] - u1[2]*u2[1];
        u3[1] = u1[2]*u2[0] - u1[0]*u2[2];
        u3[2] = u1[0]*u2[1] - u1[1]*u2[0];

        // R = v1 u1^T + v2 u2^T + v3 u3^T   (proper Kabsch rotation, det handled)
        float R[3][3];
        #pragma unroll
        for (int a = 0; a < 3; ++a)
            #pragma unroll
            for (int b = 0; b < 3; ++b)
                R[a][b] = v1[a]*u1[b] + v2[a]*u2[b] + v3[a]*u3[b];

        // ---------------- T = R * (tempJ - t0) for all 21 joints ----------------
        float T[21][3];
        #pragma unroll
        for (int k = 0; k < 21; ++k) {
            float px = sm[base + 3*k + 0] - t0x;
            float py = sm[base + 3*k + 1] - t0y;
            float pz = sm[base + 3*k + 2] - t0z;
            T[k][0] = R[0][0]*px + R[0][1]*py + R[0][2]*pz;
            T[k][1] = R[1][0]*px + R[1][1]*py + R[1][2]*pz;
            T[k][2] = R[2][0]*px + R[2][1]*py + R[2][2]*pz;
        }

        // ---------------- kinematic chain: bone length + flex clamp ----------------
        const int PA[15] = {1,2,3, 4,5,6, 7,8,9, 10,11,12, 13,14,15};
        const int GP[15] = {0,1,2, 0,4,5, 0,7,8, 0,10,11, 0,13,14};
        #pragma unroll
        for (int i = 0; i < 15; ++i) {
            const int ch = CH[i], pa = PA[i], gp = GP[i];
            // bone length from raw template (wrist offset cancels)
            float bx = sm[base + 3*ch + 0] - sm[base + 3*pa + 0];
            float by = sm[base + 3*ch + 1] - sm[base + 3*pa + 1];
            float bz = sm[base + 3*ch + 2] - sm[base + 3*pa + 2];
            float blen = sqrtf(bx*bx + by*by + bz*bz);

            float v1x = jc[i][0] - T[pa][0];
            float v1y = jc[i][1] - T[pa][1];
            float v1z = jc[i][2] - T[pa][2];
            float dis = sqrtf(v1x*v1x + v1y*v1y + v1z*v1z);
            float sc  = blen / (dis + 1e-8f);
            float vbx = v1x * sc, vby = v1y * sc, vbz = v1z * sc;

            // flex clamp: ang = atan2(|v0 x vb|, v0.vb); clip to [0, pi/2]
            float v0x = T[pa][0] - T[gp][0];
            float v0y = T[pa][1] - T[gp][1];
            float v0z = T[pa][2] - T[gp][2];
            float crx = v0y*vbz - v0z*vby;
            float cry = v0z*vbx - v0x*vbz;
            float crz = v0x*vby - v0y*vbx;
            float cdot = v0x*vbx + v0y*vby + v0z*vbz;

            float nx = vbx, ny = vby, nz = vbz;
            if (cdot < 0.0f) {   // ang > pi/2: rotate by delta = pi/2 - ang
                float s2   = crx*crx + cry*cry + crz*crz;
                float sN   = sqrtf(s2);
                float rinv = rsqrtf(s2 + cdot*cdot);
                float cd = sN * rinv;        // cos(delta) = sin(ang)
                float sd = cdot * rinv;      // sin(delta) = cos(ang) (<0)
                float ainv = 1.0f / (sN + 1e-8f);
                float ax = crx * ainv, ay = cry * ainv, az = crz * ainv;
                float adv = ax*vbx + ay*vby + az*vbz;
                float om  = (1.0f - cd) * adv;
                float cavx = ay*vbz - az*vby;
                float cavy = az*vbx - ax*vbz;
                float cavz = ax*vby - ay*vbx;
                nx = vbx*cd + cavx*sd + ax*om;
                ny = vby*cd + cavy*sd + ay*om;
                nz = vbz*cd + cavz*sd + az*om;
            }
            T[ch][0] = T[pa][0] + nx;
            T[ch][1] = T[pa][1] + ny;
            T[ch][2] = T[pa][2] + nz;
        }

        // write result into own smem row (conflict-free, own-row only)
        #pragma unroll
        for (int k = 0; k < 21; ++k) {
            sm[base + 3*k + 0] = T[k][0] + wx;
            sm[base + 3*k + 1] = T[k][1] + wy;
            sm[base + 3*k + 2] = T[k][2] + wz;
        }
    }
    __syncthreads();

    // ---------------- coalesced float4 store ----------------
    {
        #pragma unroll
        for (int i = 0; i < 16; ++i) {
            int idx = (i * TPB + tid) * 4;
            if (idx < TPB * ROW) {
                long long g = gbase + idx;
                if (g + 3 < total) {
                    *reinterpret_cast<float4*>(&out[g]) =
                        *reinterpret_cast<const float4*>(&sm[idx]);
                } else {
                    #pragma unroll
                    for (int j = 0; j < 4; ++j)
                        if (g + j < total) out[g + j] = sm[idx + j];
                }
            }
        }
    }
}

extern "C" void kernel_launch(void* const* d_in, const int* in_sizes, int n_in,
                              void* d_out, int out_size)
{
    const float* joints = (const float*)d_in[0];
    const float* tempJ  = (const float*)d_in[1];
    float* out = (float*)d_out;
    const int n = in_sizes[0] / ROW;     // 131072
    const int blocks = (n + TPB - 1) / TPB;
    kin_kernel<<<blocks, TPB>>>(joints, tempJ, out, n);
}

// round 3
// speedup vs baseline: 2.7324x; 2.7324x over previous
#include <cuda_runtime.h>

#define TPB 128
#define ROW 63            // 21 joints * 3
#define NV4 (TPB*ROW/4)   // 2016 float4 per block

__global__ void __launch_bounds__(TPB, 4)
kin_kernel(const float* __restrict__ joints,
           const float* __restrict__ tempJ,
           float* __restrict__ out, int n)
{
    __shared__ float sm[TPB * ROW];   // 32256 B, single buffer reused 3x
    const int tid = threadIdx.x;
    const long long total = (long long)n * ROW;
    const long long gbase = (long long)blockIdx.x * (TPB * ROW);
    const bool full = (gbase + TPB * ROW) <= total;
    const bool active = ((long long)blockIdx.x * TPB + tid) < n;
    const int base = tid * ROW;

    const int PALM5[5] = {1, 4, 7, 10, 13};
    const int CH[15] = {2,3,17, 5,6,18, 8,9,20, 11,12,19, 14,15,16};
    const int PA[15] = {1,2,3, 4,5,6, 7,8,9, 10,11,12, 13,14,15};

    // ================= stage tempJ (coalesced float4) =================
    if (full) {
        #pragma unroll
        for (int i = 0; i < 16; ++i) {
            int q = i * TPB + tid;
            if (q < NV4)
                reinterpret_cast<float4*>(sm)[q] =
                    reinterpret_cast<const float4*>(tempJ + gbase)[q];
        }
    } else {
        for (int q = tid; q < TPB * ROW; q += TPB) {
            long long g = gbase + q;
            if (g < total) sm[q] = tempJ[g];
        }
    }
    __syncthreads();

    // extract from template: centered palm points + bone lengths
    float sp[5][3];
    float blen[15];
    if (active) {
        const float t0x = sm[base + 0], t0y = sm[base + 1], t0z = sm[base + 2];
        #pragma unroll
        for (int p = 0; p < 5; ++p) {
            sp[p][0] = sm[base + 3 * PALM5[p] + 0] - t0x;
            sp[p][1] = sm[base + 3 * PALM5[p] + 1] - t0y;
            sp[p][2] = sm[base + 3 * PALM5[p] + 2] - t0z;
        }
        #pragma unroll
        for (int i = 0; i < 15; ++i) {
            float bx = sm[base + 3*CH[i] + 0] - sm[base + 3*PA[i] + 0];
            float by = sm[base + 3*CH[i] + 1] - sm[base + 3*PA[i] + 1];
            float bz = sm[base + 3*CH[i] + 2] - sm[base + 3*PA[i] + 2];
            blen[i] = sqrtf(bx*bx + by*by + bz*bz);
        }
    }
    __syncthreads();

    // ================= stage joints (overwrite same buffer) =================
    if (full) {
        #pragma unroll
        for (int i = 0; i < 16; ++i) {
            int q = i * TPB + tid;
            if (q < NV4)
                reinterpret_cast<float4*>(sm)[q] =
                    reinterpret_cast<const float4*>(joints + gbase)[q];
        }
    } else {
        for (int q = tid; q < TPB * ROW; q += TPB) {
            long long g = gbase + q;
            if (g < total) sm[q] = joints[g];
        }
    }
    __syncthreads();

    if (active) {
        const float wx = sm[base + 0], wy = sm[base + 1], wz = sm[base + 2];

        // ---- H = sum_palm src ⊗ dst  (src = centered template, dst = centered joints)
        float H[3][3] = {{0,0,0},{0,0,0},{0,0,0}};
        #pragma unroll
        for (int p = 0; p < 5; ++p) {
            float jx = sm[base + 3 * PALM5[p] + 0] - wx;
            float jy = sm[base + 3 * PALM5[p] + 1] - wy;
            float jz = sm[base + 3 * PALM5[p] + 2] - wz;
            H[0][0] += sp[p][0]*jx; H[0][1] += sp[p][0]*jy; H[0][2] += sp[p][0]*jz;
            H[1][0] += sp[p][1]*jx; H[1][1] += sp[p][1]*jy; H[1][2] += sp[p][1]*jz;
            H[2][0] += sp[p][2]*jx; H[2][1] += sp[p][2]*jy; H[2][2] += sp[p][2]*jz;
        }

        // ---- A = H^T H ; Jacobi eigen (V accumulates rotations, det=+1) ----
        float A[3][3];
        #pragma unroll
        for (int a = 0; a < 3; ++a)
            #pragma unroll
            for (int b = 0; b < 3; ++b)
                A[a][b] = H[0][a]*H[0][b] + H[1][a]*H[1][b] + H[2][a]*H[2][b];

        float V[3][3] = {{1,0,0},{0,1,0},{0,0,1}};
        #pragma unroll
        for (int sweep = 0; sweep < 5; ++sweep) {
            #pragma unroll
            for (int pair = 0; pair < 3; ++pair) {
                const int p = (pair == 2) ? 1 : 0;
                const int q = (pair == 0) ? 1 : 2;
                float apq = A[p][q];
                if (fabsf(apq) > 1e-30f) {
                    float tau = (A[q][q] - A[p][p]) / (2.0f * apq);
                    float t = 1.0f / (fabsf(tau) + sqrtf(1.0f + tau * tau));
                    t = copysignf(t, tau);
                    float c = rsqrtf(1.0f + t * t);
                    float s = t * c;
                    A[p][p] -= t * apq;
                    A[q][q] += t * apq;
                    A[p][q] = 0.f; A[q][p] = 0.f;
                    const int r = 3 - p - q;
                    float arp = A[r][p], arq = A[r][q];
                    A[r][p] = c * arp - s * arq; A[p][r] = A[r][p];
                    A[r][q] = s * arp + c * arq; A[q][r] = A[r][q];
                    #pragma unroll
                    for (int k = 0; k < 3; ++k) {
                        float vp = V[k][p], vq = V[k][q];
                        V[k][p] = c * vp - s * vq;
                        V[k][q] = s * vp + c * vq;
                    }
                }
            }
        }

        // sort eigenvalues (descending) -> columns v1, v2; v3 = v1 x v2
        float e0 = A[0][0], e1 = A[1][1], e2 = A[2][2];
        int i0 = 0; float em = e0;
        if (e1 > em) { i0 = 1; em = e1; }
        if (e2 > em) { i0 = 2; em = e2; }
        const int a1 = (i0 + 1) % 3, b1 = (i0 + 2) % 3;
        float ea = (a1 == 0) ? e0 : (a1 == 1) ? e1 : e2;
        float eb = (b1 == 0) ? e0 : (b1 == 1) ? e1 : e2;
        const int i1 = (ea >= eb) ? a1 : b1;

        float v1[3], v2[3], v3[3];
        #pragma unroll
        for (int k = 0; k < 3; ++k) {
            v1[k] = (i0 == 0) ? V[k][0] : (i0 == 1) ? V[k][1] : V[k][2];
            v2[k] = (i1 == 0) ? V[k][0] : (i1 == 1) ? V[k][1] : V[k][2];
        }
        v3[0] = v1[1]*v2[2] - v1[2]*v2[1];
        v3[1] = v1[2]*v2[0] - v1[0]*v2[2];
        v3[2] = v1[0]*v2[1] - v1[1]*v2[0];

        // u1 = norm(H v1); u2 = norm(GS(H v2)); u3 = u1 x u2
        float u1[3], u2[3], u3[3];
        #pragma unroll
        for (int k = 0; k < 3; ++k)
            u1[k] = H[k][0]*v1[0] + H[k][1]*v1[1] + H[k][2]*v1[2];
        {
            float inv = rsqrtf(u1[0]*u1[0] + u1[1]*u1[1] + u1[2]*u1[2] + 1e-30f);
            u1[0] *= inv; u1[1] *= inv; u1[2] *= inv;
        }
        #pragma unroll
        for (int k = 0; k < 3; ++k)
            u2[k] = H[k][0]*v2[0] + H[k][1]*v2[1] + H[k][2]*v2[2];
        {
            float pr = u1[0]*u2[0] + u1[1]*u2[1] + u1[2]*u2[2];
            u2[0] -= pr * u1[0]; u2[1] -= pr * u1[1]; u2[2] -= pr * u1[2];
            float inv = rsqrtf(u2[0]*u2[0] + u2[1]*u2[1] + u2[2]*u2[2] + 1e-30f);
            u2[0] *= inv; u2[1] *= inv; u2[2] *= inv;
        }
        u3[0] = u1[1]*u2[2] - u1[2]*u2[1];
        u3[1] = u1[2]*u2[0] - u1[0]*u2[2];
        u3[2] = u1[0]*u2[1] - u1[1]*u2[0];

        // R = v1 u1^T + v2 u2^T + v3 u3^T
        float R[3][3];
        #pragma unroll
        for (int a = 0; a < 3; ++a)
            #pragma unroll
            for (int b = 0; b < 3; ++b)
                R[a][b] = v1[a]*u1[b] + v2[a]*u2[b] + v3[a]*u3[b];

        // ---- rotated template palm points; write palm outputs in place ----
        float Tp[5][3];
        #pragma unroll
        for (int p = 0; p < 5; ++p) {
            Tp[p][0] = R[0][0]*sp[p][0] + R[0][1]*sp[p][1] + R[0][2]*sp[p][2];
            Tp[p][1] = R[1][0]*sp[p][0] + R[1][1]*sp[p][1] + R[1][2]*sp[p][2];
            Tp[p][2] = R[2][0]*sp[p][0] + R[2][1]*sp[p][1] + R[2][2]*sp[p][2];
            sm[base + 3*PALM5[p] + 0] = Tp[p][0] + wx;
            sm[base + 3*PALM5[p] + 1] = Tp[p][1] + wy;
            sm[base + 3*PALM5[p] + 2] = Tp[p][2] + wz;
        }
        // wrist slot already holds w (T[0] = 0)

        // ---- kinematic chain, finger-major; rolling (gpT, paT) ----
        #pragma unroll
        for (int f = 0; f < 5; ++f) {
            float gx = 0.f, gy = 0.f, gz = 0.f;            // T[grandparent] = T[0]
            float px = Tp[f][0], py = Tp[f][1], pz = Tp[f][2]; // T[parent] = palm base
            #pragma unroll
            for (int k = 0; k < 3; ++k) {
                const int i = 3 * f + k;
                const int ch = CH[i];

                // bone-length normalized direction from observed child joint
                float v1x = (sm[base + 3*ch + 0] - wx) - px;
                float v1y = (sm[base + 3*ch + 1] - wy) - py;
                float v1z = (sm[base + 3*ch + 2] - wz) - pz;
                float d2  = v1x*v1x + v1y*v1y + v1z*v1z;
                float scl = blen[i] * rsqrtf(d2 + 1e-24f);
                float vbx = v1x * scl, vby = v1y * scl, vbz = v1z * scl;

                // flex clamp: angle(v0, vb) clipped to [0, pi/2]
                float v0x = px - gx, v0y = py - gy, v0z = pz - gz;
                float crx = v0y*vbz - v0z*vby;
                float cry = v0z*vbx - v0x*vbz;
                float crz = v0x*vby - v0y*vbx;
                float cdot = v0x*vbx + v0y*vby + v0z*vbz;

                float nx = vbx, ny = vby, nz = vbz;
                if (cdot < 0.0f) {   // ang > pi/2: rotate by delta = pi/2 - ang
                    float s2   = crx*crx + cry*cry + crz*crz;
                    float sN   = sqrtf(s2);
                    float rinv = rsqrtf(s2 + cdot*cdot);
                    float cd = sN * rinv;        // cos(delta)
                    float sd = cdot * rinv;      // sin(delta) (<0)
                    float ainv = rsqrtf(s2 + 1e-30f);
                    float ax = crx * ainv, ay = cry * ainv, az = crz * ainv;
                    float adv = ax*vbx + ay*vby + az*vbz;
                    float om  = (1.0f - cd) * adv;
                    float cavx = ay*vbz - az*vby;
                    float cavy = az*vbx - ax*vbz;
                    float cavz = ax*vby - ay*vbx;
                    nx = vbx*cd + cavx*sd + ax*om;
                    ny = vby*cd + cavy*sd + ay*om;
                    nz = vbz*cd + cavz*sd + az*om;
                }
                float cx = px + nx, cy = py + ny, cz = pz + nz;

                // child's raw joint value is dead now -> write output in place
                sm[base + 3*ch + 0] = cx + wx;
                sm[base + 3*ch + 1] = cy + wy;
                sm[base + 3*ch + 2] = cz + wz;

                gx = px; gy = py; gz = pz;
                px = cx; py = cy; pz = cz;
            }
        }
    }
    __syncthreads();

    // ================= coalesced float4 store =================
    if (full) {
        #pragma unroll
        for (int i = 0; i < 16; ++i) {
            int q = i * TPB + tid;
            if (q < NV4)
                reinterpret_cast<float4*>(out + gbase)[q] =
                    reinterpret_cast<const float4*>(sm)[q];
        }
    } else {
        for (int q = tid; q < TPB * ROW; q += TPB) {
            long long g = gbase + q;
            if (g < total) out[g] = sm[q];
        }
    }
}

extern "C" void kernel_launch(void* const* d_in, const int* in_sizes, int n_in,
                              void* d_out, int out_size)
{
    const float* joints = (const float*)d_in[0];
    const float* tempJ  = (const float*)d_in[1];
    float* out = (float*)d_out;
    const int n = in_sizes[0] / ROW;     // 131072
    const int blocks = (n + TPB - 1) / TPB;
    kin_kernel<<<blocks, TPB>>>(joints, tempJ, out, n);
}